// round 9
// baseline (speedup 1.0000x reference)
#include <cuda_runtime.h>
#include <cstdint>
#include <cstddef>

// ---------------- device scratch (module globals: allocation-free) ----------------
#define NODES_MAX 4096
#define SMAX 64
__device__ int g_order[NODES_MAX];
__device__ int g_segStart[SMAX];
__device__ int g_segCount[SMAX];

// ---------------- grouping kernel: counting sort of nodes by species ----------------
__global__ void group_kernel(const int* __restrict__ index, int N) {
    __shared__ int cnt[SMAX];
    __shared__ int cur[SMAX];
    int tid = threadIdx.x;
    if (tid < SMAX) cnt[tid] = 0;
    __syncthreads();
    for (int i = tid; i < N; i += blockDim.x)
        atomicAdd(&cnt[index[i] & (SMAX - 1)], 1);
    __syncthreads();
    if (tid == 0) {
        int run = 0;
        for (int s = 0; s < SMAX; s++) {
            g_segStart[s] = run;
            g_segCount[s] = cnt[s];
            cur[s] = run;
            run += cnt[s];
        }
    }
    __syncthreads();
    for (int i = tid; i < N; i += blockDim.x) {
        int s = index[i] & (SMAX - 1);
        int p = atomicAdd(&cur[s], 1);
        if (p < NODES_MAX) g_order[p] = i;
    }
}

// ---------------- f32x2 helpers ----------------
typedef unsigned long long ull;
static __device__ __forceinline__ ull pk2(float v) {        // (v, v)
    ull r;
    asm("mov.b64 %0, {%1, %1};" : "=l"(r) : "r"(__float_as_uint(v)));
    return r;
}
static __device__ __forceinline__ ull pkab(float a, float b) {  // (a, b)
    ull r;
    asm("mov.b64 %0, {%1, %2};" : "=l"(r) : "r"(__float_as_uint(a)), "r"(__float_as_uint(b)));
    return r;
}
static __device__ __forceinline__ void fma2(ull& d, ull a, ull b) {
    asm("fma.rn.f32x2 %0, %1, %2, %0;" : "+l"(d) : "l"(a), "l"(b));
}
static __device__ __forceinline__ float lo2(ull v) {
    unsigned int a, b;
    asm("mov.b64 {%0, %1}, %2;" : "=r"(a), "=r"(b) : "l"(v));
    return __uint_as_float(a);
}
static __device__ __forceinline__ float hi2(ull v) {
    unsigned int a, b;
    asm("mov.b64 {%0, %1}, %2;" : "=r"(a), "=r"(b) : "l"(v));
    return __uint_as_float(b);
}

// ---------------- layout ----------------
// Per channel c the output row base o=(n*128+c)*729 satisfies o mod 4 == c mod 4.
// Phase h(c) = (-c) mod 4: quads cover elements [h, h+4*Kq), head/tail scalar.
// uw smem stores element e of channel c at j*JSTR + (e - h)  (head wrapped to end),
// so quad LDS.128 at j*JSTR + 4*q is 16B-aligned.
#define CT 8
#define JSTR 732
#define CHSTR (9 * JSTR)               // 6588
#define UW_F (CT * CHSTR)              // 52704
#define WS_OFF UW_F
#define SMEM_BYTES ((UW_F + 240) * 4)  // 211,776 B

// ---------------- build helper ----------------
template<int MUL, int IRR, int KOFF, int IBASE>
static __device__ __forceinline__ void build_chunk(const float* __restrict__ up,
                                                   const float* __restrict__ ws,
                                                   float* __restrict__ uw, int tid) {
    for (int idx = tid; idx < 729 * IRR; idx += 512) {
        int ab  = idx / (9 * IRR);
        int rem = idx - ab * 9 * IRR;
        int j   = rem / IRR;
        int il  = rem - j * IRR;
        const float* ub = up + ((ab * 9 + j) * MUL) * IRR + il;
        float uv[MUL];
        #pragma unroll
        for (int k = 0; k < MUL; k++) uv[k] = __ldg(ub + k * IRR);
        float acc[8];
        #pragma unroll
        for (int c = 0; c < 8; c++) acc[c] = 0.f;
        #pragma unroll
        for (int k = 0; k < MUL; k++) {
            const float* wr = ws + (KOFF + k) * 8;
            #pragma unroll
            for (int c = 0; c < 8; c++) acc[c] += uv[k] * wr[c];
        }
        int e = ab * 9 + IBASE + il;
        #pragma unroll
        for (int c = 0; c < 8; c++) {
            const int hc = (4 - (c & 3)) & 3;
            int pos = (e >= hc) ? (e - hc) : (729 - hc + e);
            uw[c * CHSTR + j * JSTR + pos] = acc[c];
        }
    }
}

// ---------------- main kernel ----------------
// grid = (C/8, S), 512 threads = 16 warps: warp -> channel (wid>>1), half (wid&1).
// 6 nodes/group as 3 f32x2 node-pairs; lane covers a 4-element quad;
// uw via aligned LDS.128 (dup-packed per element); STG.128 streaming stores.
__global__ __launch_bounds__(512, 1)
void mace_kernel(const float* __restrict__ nf,
                 const float* __restrict__ u0, const float* __restrict__ u1,
                 const float* __restrict__ u2,
                 const float* __restrict__ w0, const float* __restrict__ w1,
                 const float* __restrict__ w2,
                 float* __restrict__ out, int C) {
    extern __shared__ float sm[];
    float* uw = sm;
    float* ws = sm + WS_OFF;

    const int s = blockIdx.y;
    const int m = g_segCount[s];
    if (m == 0) return;             // CTA-uniform, before any barrier
    const int c0 = blockIdx.x * CT;
    const int segBase = g_segStart[s];
    const int tid = threadIdx.x;

    // ---- stage scaled species weights: ws[kglobal][c] ----
    if (tid < 240) {
        int kg = tid >> 3, c = tid & 7;
        const float* wp; int k; float scale; int mul;
        if (kg < 7)       { wp = w0; k = kg;      scale = 0.61478815f; mul = 7;  }
        else if (kg < 18) { wp = w1; k = kg - 7;  scale = 0.54910049f; mul = 11; }
        else              { wp = w2; k = kg - 18; scale = 0.53728497f; mul = 12; }
        ws[tid] = wp[((size_t)s * mul + k) * C + (c0 + c)] * scale;
    }
    __syncthreads();

    // ---- build uw (shifted layout) ----
    build_chunk<7, 1, 0, 0>(u0, ws, uw, tid);
    build_chunk<11, 3, 7, 1>(u1, ws, uw, tid);
    build_chunk<12, 5, 18, 4>(u2, ws, uw, tid);
    __syncthreads();

    // ---- main loop: 6 nodes per group ----
    const int lane = tid & 31;
    const int wid  = tid >> 5;          // 0..15
    const int cw   = wid >> 1;          // channel in tile
    const int q    = wid & 1;           // node-group half
    const int crow = c0 + cw;
    const float* uwC = uw + cw * CHSTR;
    const int h  = (4 - (crow & 3)) & 3;  // warp-uniform phase
    const int Kq = (729 - h) >> 2;        // full quads
    const int nL = 729 - 4 * Kq;          // leftover scalars (<=5)

    const int groups = (m + 5) / 6;
    for (int g = q; g < groups; g += 2) {
        // gather 54 x-values (6 nodes x 9 j): v0 = el 0..31, v1 = el 32..53 (lanes 0..21)
        int n0 = lane / 9, j0 = lane - n0 * 9;
        int idx0 = g * 6 + n0;
        if (idx0 >= m) idx0 = m - 1;               // clamp: safe read, store masked
        int nid0 = g_order[segBase + idx0];
        float v0 = nf[((size_t)nid0 * C + crow) * 9 + j0];

        int nid1 = 0;
        float v1 = 0.f;
        if (lane < 22) {
            int el1 = 32 + lane;
            int n1 = el1 / 9, j1 = el1 - n1 * 9;
            int idx1 = g * 6 + n1;
            if (idx1 >= m) idx1 = m - 1;
            nid1 = g_order[segBase + idx1];
            v1 = nf[((size_t)nid1 * C + crow) * 9 + j1];
        }

        // node ids: nd 0..3 from v0 lanes 0,9,18,27; nd 4,5 from v1 lanes 4,13
        unsigned o[6];
        bool valid[6];
        #pragma unroll
        for (int nd = 0; nd < 6; nd++) {
            int nn = (nd < 4) ? __shfl_sync(0xffffffffu, nid0, nd * 9)
                              : __shfl_sync(0xffffffffu, nid1, nd * 9 - 32);
            valid[nd] = (g * 6 + nd) < m;
            o[nd] = (unsigned)(nn * C + crow) * 729u;
        }

        // pack x node-pairs: xp[p][j] = (x[2p][j], x[2p+1][j])
        ull xp[3][9];
        #pragma unroll
        for (int j = 0; j < 9; j++) {
            float a0 = __shfl_sync(0xffffffffu, v0, j);
            float b0 = __shfl_sync(0xffffffffu, v0, 9 + j);
            xp[0][j] = pkab(a0, b0);
            float a1 = __shfl_sync(0xffffffffu, v0, 18 + j);
            int eb = 27 + j;
            float b1 = (eb < 32) ? __shfl_sync(0xffffffffu, v0, eb)
                                 : __shfl_sync(0xffffffffu, v1, eb - 32);
            xp[1][j] = pkab(a1, b1);
            float a2 = __shfl_sync(0xffffffffu, v1, 4 + j);
            float b2 = __shfl_sync(0xffffffffu, v1, 13 + j);
            xp[2][j] = pkab(a2, b2);
        }

        // body: quads qi = it*32 + lane, elements E = h + 4*qi
        #pragma unroll 1
        for (int it = 0; it < 6; it++) {
            int qi = it * 32 + lane;
            bool act = qi < Kq;
            int qc = act ? qi : 0;
            int soff = 4 * qc;
            // acc[e4][p]: element-in-quad x node-pair
            ull aq0[3] = {0ull, 0ull, 0ull};
            ull aq1[3] = {0ull, 0ull, 0ull};
            ull aq2[3] = {0ull, 0ull, 0ull};
            ull aq3[3] = {0ull, 0ull, 0ull};
            #pragma unroll
            for (int j = 0; j < 9; j++) {
                float4 uf = *reinterpret_cast<const float4*>(uwC + j * JSTR + soff);
                ull d0 = pk2(uf.x), d1 = pk2(uf.y), d2 = pk2(uf.z), d3 = pk2(uf.w);
                #pragma unroll
                for (int p = 0; p < 3; p++) {
                    fma2(aq0[p], d0, xp[p][j]);
                    fma2(aq1[p], d1, xp[p][j]);
                    fma2(aq2[p], d2, xp[p][j]);
                    fma2(aq3[p], d3, xp[p][j]);
                }
            }
            int E = h + 4 * qc;
            #pragma unroll
            for (int p = 0; p < 3; p++) {
                if (act && valid[2 * p]) {
                    float4 f4;
                    f4.x = lo2(aq0[p]); f4.y = lo2(aq1[p]);
                    f4.z = lo2(aq2[p]); f4.w = lo2(aq3[p]);
                    __stcs(reinterpret_cast<float4*>(out + o[2 * p] + E), f4);
                }
                if (act && valid[2 * p + 1]) {
                    float4 f4;
                    f4.x = hi2(aq0[p]); f4.y = hi2(aq1[p]);
                    f4.z = hi2(aq2[p]); f4.w = hi2(aq3[p]);
                    __stcs(reinterpret_cast<float4*>(out + o[2 * p + 1] + E), f4);
                }
            }
        }

        // leftovers: head elements [0,h) and tail [h+4Kq, 729): nL lanes
        if (lane < nL) {
            int e   = (lane < h) ? lane : (4 * Kq + lane);
            int pos = (lane < h) ? (729 - h + lane) : (4 * Kq + lane - h);
            float b[6] = {0.f, 0.f, 0.f, 0.f, 0.f, 0.f};
            #pragma unroll
            for (int j = 0; j < 9; j++) {
                float uvv = uwC[j * JSTR + pos];
                #pragma unroll
                for (int p = 0; p < 3; p++) {
                    b[2 * p]     += uvv * lo2(xp[p][j]);
                    b[2 * p + 1] += uvv * hi2(xp[p][j]);
                }
            }
            #pragma unroll
            for (int nd = 0; nd < 6; nd++)
                if (valid[nd]) __stcs(out + o[nd] + e, b[nd]);
        }
    }
}

// ---------------- launch ----------------
extern "C" void kernel_launch(void* const* d_in, const int* in_sizes, int n_in,
                              void* d_out, int out_size) {
    const float *nf = nullptr, *u0 = nullptr, *u1 = nullptr, *u2 = nullptr;
    const float *w0 = nullptr, *w1 = nullptr, *w2 = nullptr;
    const int* index = nullptr;
    int N = 0, nf_sz = 0, w0_sz = 0;
    for (int i = 0; i < n_in; i++) {
        int sz = in_sizes[i];
        switch (sz) {
            case 5103:    u0 = (const float*)d_in[i]; break;
            case 24057:   u1 = (const float*)d_in[i]; break;
            case 43740:   u2 = (const float*)d_in[i]; break;
            case 44800:   w0 = (const float*)d_in[i]; w0_sz = sz; break;
            case 70400:   w1 = (const float*)d_in[i]; break;
            case 76800:   w2 = (const float*)d_in[i]; break;
            case 2048:    index = (const int*)d_in[i]; N = sz; break;
            case 2359296: nf = (const float*)d_in[i]; nf_sz = sz; break;
            default: break;
        }
    }
    if (!nf || !index || !u0 || !u1 || !u2 || !w0 || !w1 || !w2) return;

    const int C = nf_sz / (N * 9);        // 128
    const int S = w0_sz / (7 * C);        // 50

    group_kernel<<<1, 256>>>(index, N);

    cudaFuncSetAttribute(mace_kernel,
                         cudaFuncAttributeMaxDynamicSharedMemorySize, SMEM_BYTES);
    dim3 grid(C / CT, S);
    mace_kernel<<<grid, 512, SMEM_BYTES>>>(nf, u0, u1, u2, w0, w1, w2,
                                           (float*)d_out, C);
}

// round 10
// speedup vs baseline: 1.0288x; 1.0288x over previous
#include <cuda_runtime.h>
#include <cstdint>
#include <cstddef>

// ---------------- device scratch (module globals: allocation-free) ----------------
#define NODES_MAX 4096
#define SMAX 64
__device__ int g_order[NODES_MAX];
__device__ int g_segStart[SMAX];
__device__ int g_segCount[SMAX];
__device__ int g_work;          // dynamic work counter (reset each launch)

// ---------------- grouping kernel: counting sort of nodes by species ----------------
__global__ void group_kernel(const int* __restrict__ index, int N) {
    __shared__ int cnt[SMAX];
    __shared__ int cur[SMAX];
    int tid = threadIdx.x;
    if (tid == 0) g_work = 0;   // reset persistent-work counter (graph-replay safe)
    if (tid < SMAX) cnt[tid] = 0;
    __syncthreads();
    for (int i = tid; i < N; i += blockDim.x)
        atomicAdd(&cnt[index[i] & (SMAX - 1)], 1);
    __syncthreads();
    if (tid == 0) {
        int run = 0;
        for (int s = 0; s < SMAX; s++) {
            g_segStart[s] = run;
            g_segCount[s] = cnt[s];
            cur[s] = run;
            run += cnt[s];
        }
    }
    __syncthreads();
    for (int i = tid; i < N; i += blockDim.x) {
        int s = index[i] & (SMAX - 1);
        int p = atomicAdd(&cur[s], 1);
        if (p < NODES_MAX) g_order[p] = i;
    }
}

// ---------------- f32x2 helpers ----------------
typedef unsigned long long ull;
static __device__ __forceinline__ ull pk2(float v) {        // (v, v)
    ull r;
    asm("mov.b64 %0, {%1, %1};" : "=l"(r) : "r"(__float_as_uint(v)));
    return r;
}
static __device__ __forceinline__ void fma2(ull& d, ull a, ull b) {
    asm("fma.rn.f32x2 %0, %1, %2, %0;" : "+l"(d) : "l"(a), "l"(b));
}
static __device__ __forceinline__ void unpk2(ull v, float& lo, float& hi) {
    unsigned int a, b;
    asm("mov.b64 {%0, %1}, %2;" : "=r"(a), "=r"(b) : "l"(v));
    lo = __uint_as_float(a);
    hi = __uint_as_float(b);
}
static __device__ __forceinline__ float lo2(ull v) {
    unsigned int a, b;
    asm("mov.b64 {%0, %1}, %2;" : "=r"(a), "=r"(b) : "l"(v));
    return __uint_as_float(a);
}

// ---------------- layout ----------------
// Per channel c the output row base o=(n*128+c)*729 satisfies o mod 4 == c mod 4.
// Phase h(c) = (-c) mod 4: quads cover elements [h, h+4*Kq), head/tail scalar.
// uw smem stores element e of channel c at j*JSTR + (e - h) (head wrapped to end),
// so quad LDS.128 at j*JSTR + 4*q is 16B-aligned.
#define CT 8
#define JSTR 732
#define CHSTR (9 * JSTR)               // 6588
#define UW_F (CT * CHSTR)              // 52704
#define WS_OFF UW_F
#define SMEM_BYTES ((UW_F + 240 + 8) * 4)

// ---------------- build helper ----------------
template<int MUL, int IRR, int KOFF, int IBASE>
static __device__ __forceinline__ void build_chunk(const float* __restrict__ up,
                                                   const float* __restrict__ ws,
                                                   float* __restrict__ uw, int tid) {
    for (int idx = tid; idx < 729 * IRR; idx += 512) {
        int ab  = idx / (9 * IRR);
        int rem = idx - ab * 9 * IRR;
        int j   = rem / IRR;
        int il  = rem - j * IRR;
        const float* ub = up + ((ab * 9 + j) * MUL) * IRR + il;
        float uv[MUL];
        #pragma unroll
        for (int k = 0; k < MUL; k++) uv[k] = __ldg(ub + k * IRR);
        float acc[8];
        #pragma unroll
        for (int c = 0; c < 8; c++) acc[c] = 0.f;
        #pragma unroll
        for (int k = 0; k < MUL; k++) {
            const float* wr = ws + (KOFF + k) * 8;
            #pragma unroll
            for (int c = 0; c < 8; c++) acc[c] += uv[k] * wr[c];
        }
        int e = ab * 9 + IBASE + il;
        #pragma unroll
        for (int c = 0; c < 8; c++) {
            const int hc = (4 - (c & 3)) & 3;
            int pos = (e >= hc) ? (e - hc) : (729 - hc + e);
            uw[c * CHSTR + j * JSTR + pos] = acc[c];
        }
    }
}

// ---------------- main kernel (persistent, dynamic work-stealing) ----------------
// 148 CTAs x 512 threads. Work item w -> (species s = w / nct, ctile = w % nct).
// Inner math = R8 core: 4 nodes/group, dup-packed x, element-pair f32x2 accs,
// aligned LDS.128 of uw, STG.128 streaming stores.
__global__ __launch_bounds__(512, 1)
void mace_kernel(const float* __restrict__ nf,
                 const float* __restrict__ u0, const float* __restrict__ u1,
                 const float* __restrict__ u2,
                 const float* __restrict__ w0, const float* __restrict__ w1,
                 const float* __restrict__ w2,
                 float* __restrict__ out, int C, int W, int nct) {
    extern __shared__ float sm[];
    float* uw = sm;
    float* ws = sm + WS_OFF;
    int* s_w = (int*)(sm + WS_OFF + 240);

    const int tid = threadIdx.x;
    const int lane = tid & 31;
    const int wid  = tid >> 5;          // 0..15
    const int cw   = wid >> 1;          // channel in tile
    const int q    = wid & 1;           // node-group half
    const float* uwC = uw + cw * CHSTR;

    for (;;) {
        __syncthreads();                 // protect smem (uw/ws/s_w) across work items
        if (tid == 0) *s_w = atomicAdd(&g_work, 1);
        __syncthreads();
        const int w = *s_w;
        if (w >= W) break;               // uniform exit

        const int s  = w / nct;
        const int c0 = (w - s * nct) * CT;
        const int m  = g_segCount[s];
        if (m == 0) continue;            // uniform
        const int segBase = g_segStart[s];

        // ---- stage scaled species weights: ws[kglobal][c] ----
        if (tid < 240) {
            int kg = tid >> 3, c = tid & 7;
            const float* wp; int k; float scale; int mul;
            if (kg < 7)       { wp = w0; k = kg;      scale = 0.61478815f; mul = 7;  }
            else if (kg < 18) { wp = w1; k = kg - 7;  scale = 0.54910049f; mul = 11; }
            else              { wp = w2; k = kg - 18; scale = 0.53728497f; mul = 12; }
            ws[tid] = wp[((size_t)s * mul + k) * C + (c0 + c)] * scale;
        }
        __syncthreads();

        // ---- build uw (shifted layout) ----
        build_chunk<7, 1, 0, 0>(u0, ws, uw, tid);
        build_chunk<11, 3, 7, 1>(u1, ws, uw, tid);
        build_chunk<12, 5, 18, 4>(u2, ws, uw, tid);
        __syncthreads();

        // ---- main loop ----
        const int crow = c0 + cw;
        const int h  = (4 - (crow & 3)) & 3;  // warp-uniform phase
        const int Kq = (729 - h) >> 2;        // full quads
        const int nL = 729 - 4 * Kq;          // leftover scalars (<=5)

        const int groups = (m + 3) >> 2;
        for (int g = q; g < groups; g += 2) {
            // gather 36 x-values (4 nodes x 9 j): v0 = el 0..31, v1 = el 32..35
            int n0 = lane / 9, j0 = lane - n0 * 9;
            int idx0 = g * 4 + n0;
            if (idx0 >= m) idx0 = m - 1;       // clamp: safe read, store masked
            int nid = g_order[segBase + idx0];
            float v0 = nf[((size_t)nid * C + crow) * 9 + j0];
            float v1 = 0.f;
            if (lane < 4) {
                int idx1 = g * 4 + 3;
                if (idx1 >= m) idx1 = m - 1;
                v1 = nf[((size_t)g_order[segBase + idx1] * C + crow) * 9 + (5 + lane)];
            }

            unsigned o[4];
            bool valid[4];
            #pragma unroll
            for (int nd = 0; nd < 4; nd++) {
                int n4 = __shfl_sync(0xffffffffu, nid, nd * 9);
                valid[nd] = (g * 4 + nd) < m;
                o[nd] = (unsigned)(n4 * C + crow) * 729u;
            }

            // dup-packed x: xd[nd][j] = (x, x)
            ull xd[4][9];
            #pragma unroll
            for (int nd = 0; nd < 4; nd++) {
                #pragma unroll
                for (int j = 0; j < 9; j++) {
                    int el = nd * 9 + j;
                    float xv = (el < 32) ? __shfl_sync(0xffffffffu, v0, el)
                                         : __shfl_sync(0xffffffffu, v1, el - 32);
                    xd[nd][j] = pk2(xv);
                }
            }

            // body: quads qi = it*32 + lane, elements E = h + 4*qi
            #pragma unroll 1
            for (int it = 0; it < 6; it++) {
                int qi = it * 32 + lane;
                bool act = qi < Kq;
                int qc = act ? qi : 0;
                int soff = 4 * qc;
                ull aA[4] = {0ull, 0ull, 0ull, 0ull};   // (E, E+1)
                ull aB[4] = {0ull, 0ull, 0ull, 0ull};   // (E+2, E+3)
                #pragma unroll
                for (int j = 0; j < 9; j++) {
                    ulonglong2 uv = *reinterpret_cast<const ulonglong2*>(uwC + j * JSTR + soff);
                    fma2(aA[0], uv.x, xd[0][j]);  fma2(aB[0], uv.y, xd[0][j]);
                    fma2(aA[1], uv.x, xd[1][j]);  fma2(aB[1], uv.y, xd[1][j]);
                    fma2(aA[2], uv.x, xd[2][j]);  fma2(aB[2], uv.y, xd[2][j]);
                    fma2(aA[3], uv.x, xd[3][j]);  fma2(aB[3], uv.y, xd[3][j]);
                }
                int E = h + 4 * qc;
                #pragma unroll
                for (int nd = 0; nd < 4; nd++) {
                    float4 f4;
                    unpk2(aA[nd], f4.x, f4.y);
                    unpk2(aB[nd], f4.z, f4.w);
                    if (act && valid[nd])
                        __stcs(reinterpret_cast<float4*>(out + o[nd] + E), f4);
                }
            }

            // leftovers: head elements [0,h) and tail [h+4Kq, 729): nL lanes
            if (lane < nL) {
                int e   = (lane < h) ? lane : (4 * Kq + lane);
                int pos = (lane < h) ? (729 - h + lane) : (4 * Kq + lane - h);
                float b0 = 0.f, b1 = 0.f, b2 = 0.f, b3 = 0.f;
                #pragma unroll
                for (int j = 0; j < 9; j++) {
                    float uvv = uwC[j * JSTR + pos];
                    b0 += uvv * lo2(xd[0][j]);
                    b1 += uvv * lo2(xd[1][j]);
                    b2 += uvv * lo2(xd[2][j]);
                    b3 += uvv * lo2(xd[3][j]);
                }
                if (valid[0]) __stcs(out + o[0] + e, b0);
                if (valid[1]) __stcs(out + o[1] + e, b1);
                if (valid[2]) __stcs(out + o[2] + e, b2);
                if (valid[3]) __stcs(out + o[3] + e, b3);
            }
        }
    }
}

// ---------------- launch ----------------
extern "C" void kernel_launch(void* const* d_in, const int* in_sizes, int n_in,
                              void* d_out, int out_size) {
    const float *nf = nullptr, *u0 = nullptr, *u1 = nullptr, *u2 = nullptr;
    const float *w0 = nullptr, *w1 = nullptr, *w2 = nullptr;
    const int* index = nullptr;
    int N = 0, nf_sz = 0, w0_sz = 0;
    for (int i = 0; i < n_in; i++) {
        int sz = in_sizes[i];
        switch (sz) {
            case 5103:    u0 = (const float*)d_in[i]; break;
            case 24057:   u1 = (const float*)d_in[i]; break;
            case 43740:   u2 = (const float*)d_in[i]; break;
            case 44800:   w0 = (const float*)d_in[i]; w0_sz = sz; break;
            case 70400:   w1 = (const float*)d_in[i]; break;
            case 76800:   w2 = (const float*)d_in[i]; break;
            case 2048:    index = (const int*)d_in[i]; N = sz; break;
            case 2359296: nf = (const float*)d_in[i]; nf_sz = sz; break;
            default: break;
        }
    }
    if (!nf || !index || !u0 || !u1 || !u2 || !w0 || !w1 || !w2) return;

    const int C = nf_sz / (N * 9);        // 128
    const int S = w0_sz / (7 * C);        // 50
    const int nct = C / CT;               // 16
    const int W = nct * S;                // 800 work items

    group_kernel<<<1, 256>>>(index, N);

    cudaFuncSetAttribute(mace_kernel,
                         cudaFuncAttributeMaxDynamicSharedMemorySize, SMEM_BYTES);
    int nCTA = 148;
    if (nCTA > W) nCTA = W;
    mace_kernel<<<nCTA, 512, SMEM_BYTES>>>(nf, u0, u1, u2, w0, w1, w2,
                                           (float*)d_out, C, W, nct);
}